// round 2
// baseline (speedup 1.0000x reference)
#include <cuda_runtime.h>
#include <cuda_fp16.h>
#include <cstdint>
#include <math.h>

// Problem dims
#define NB   32      // batch
#define NI   12      // input channels
#define NVV  128     // vertices
#define NHD  32      // conv hidden
#define NTT  100     // time steps
#define NHH  4096    // NH = V*H
#define NH3  12288   // 3*NH
#define NR   3200    // T*B rows

// d_out region offsets (floats)
static const long OUT_STATES = 13107200L;   // B*NH*T
static const long OUT_HENC   = 26214400L;   // + B*NH*T
static const long OUT_CLS    = 26345472L;   // + B*NH

// ------------------------- scratch (device globals, no allocs) -----------
__device__ float   gSupport[NVV * NVV];
__device__ __half  gReprH[(long)NR * NHH];       // 26 MB
__device__ __half  gWih[(long)NH3 * NHH];        // 100 MB
__device__ __half  gWhh[(long)NH3 * NHH];        // 100 MB
__device__ float   gGx[(long)NR * NH3];          // 157 MB
__device__ float   gGh[NB * NH3];
__device__ float   gH[NB * NHH];
__device__ __half  gHh[NB * NHH];

// ------------------------- weight conversion ------------------------------
__global__ void convert_weights_kernel(const float* __restrict__ wih,
                                       const float* __restrict__ whh) {
    long n = (long)NH3 * NHH;
    long stride = (long)gridDim.x * blockDim.x;
    for (long i = (long)blockIdx.x * blockDim.x + threadIdx.x; i < n; i += stride) {
        gWih[i] = __float2half(wih[i]);
        gWhh[i] = __float2half(whh[i]);
    }
}

// ------------------------- support = adj / (rowsum + 1e-6) ---------------
__global__ void support_kernel(const float* __restrict__ adj) {
    int w = threadIdx.x;  // 128 threads
    float s = 0.f;
    for (int v = 0; v < NVV; v++) s += adj[w * NVV + v];
    float inv = 1.f / (s + 1e-6f);
    for (int v = 0; v < NVV; v++) gSupport[w * NVV + v] = adj[w * NVV + v] * inv;
}

// ------------------------- repr: conv + 2x graph conv --------------------
// One block per (t,b). Writes representations (fp32 to d_out) and gReprH (fp16).
__global__ void repr_kernel(const float* __restrict__ x,
                            const float* __restrict__ conv_w,
                            const float* __restrict__ conv_b,
                            float* __restrict__ d_out) {
    extern __shared__ float sm[];
    float* supT = sm;                  // [128][129]  supT[v][w] = support[w][v]
    float* bufA = supT + 128 * 129;    // [32][132]
    float* bufB = bufA + 32 * 132;     // [32][132]
    float* xs   = bufB + 32 * 132;     // [12][128]

    int r = blockIdx.x;
    int t = r >> 5;
    int b = r & 31;
    int tid = threadIdx.x;

    // stage x slice: x[b][i][v][t]
    for (int idx = tid; idx < NI * NVV; idx += 256) {
        int i = idx >> 7, v = idx & 127;
        xs[idx] = x[(((long)b * NI + i) * NVV + v) * NTT + t];
    }
    // stage support transposed
    for (int idx = tid; idx < NVV * NVV; idx += 256) {
        int w = idx >> 7, v = idx & 127;
        supT[v * 129 + w] = gSupport[idx];
    }
    __syncthreads();

    // x_in[h][v]
    for (int idx = tid; idx < NHD * NVV; idx += 256) {
        int h = idx >> 7, v = idx & 127;
        float a = conv_b[h];
#pragma unroll
        for (int i = 0; i < NI; i++) a += conv_w[h * NI + i] * xs[i * NVV + v];
        bufA[h * 132 + v] = a;
    }
    __syncthreads();

    int w0 = tid & 31;
    int h0 = tid >> 5;  // 0..7

    // x1 = x_in @ supT
    float acc1[4][4];
#pragma unroll
    for (int i = 0; i < 4; i++)
#pragma unroll
        for (int j = 0; j < 4; j++) acc1[i][j] = 0.f;
    for (int v = 0; v < NVV; v++) {
        float a[4], s[4];
#pragma unroll
        for (int i = 0; i < 4; i++) a[i] = bufA[(h0 + 8 * i) * 132 + v];
#pragma unroll
        for (int j = 0; j < 4; j++) s[j] = supT[v * 129 + w0 + 32 * j];
#pragma unroll
        for (int i = 0; i < 4; i++)
#pragma unroll
            for (int j = 0; j < 4; j++) acc1[i][j] += a[i] * s[j];
    }
    __syncthreads();
#pragma unroll
    for (int i = 0; i < 4; i++)
#pragma unroll
        for (int j = 0; j < 4; j++) bufB[(h0 + 8 * i) * 132 + w0 + 32 * j] = acc1[i][j];
    __syncthreads();

    // x2 = x1 @ supT
    float acc2[4][4];
#pragma unroll
    for (int i = 0; i < 4; i++)
#pragma unroll
        for (int j = 0; j < 4; j++) acc2[i][j] = 0.f;
    for (int v = 0; v < NVV; v++) {
        float a[4], s[4];
#pragma unroll
        for (int i = 0; i < 4; i++) a[i] = bufB[(h0 + 8 * i) * 132 + v];
#pragma unroll
        for (int j = 0; j < 4; j++) s[j] = supT[v * 129 + w0 + 32 * j];
#pragma unroll
        for (int i = 0; i < 4; i++)
#pragma unroll
            for (int j = 0; j < 4; j++) acc2[i][j] += a[i] * s[j];
    }

    // write representations + fp16 repr
#pragma unroll
    for (int i = 0; i < 4; i++) {
#pragma unroll
        for (int j = 0; j < 4; j++) {
            int h = h0 + 8 * i, w = w0 + 32 * j;
            int n = h * NVV + w;
            float val = acc2[i][j];
            d_out[(long)b * (NHH * NTT) + (long)n * NTT + t] = val;
            gReprH[(long)r * NHH + n] = __float2half(val);
        }
    }
}

// ------------------------- fp16 NT GEMM (mma.sync m16n8k16) --------------
__device__ __forceinline__ void mma_m16n8k16(float* d, const uint32_t* a,
                                             uint32_t b0, uint32_t b1) {
    asm volatile(
        "mma.sync.aligned.m16n8k16.row.col.f32.f16.f16.f32 "
        "{%0,%1,%2,%3}, {%4,%5,%6,%7}, {%8,%9}, {%0,%1,%2,%3};\n"
        : "+f"(d[0]), "+f"(d[1]), "+f"(d[2]), "+f"(d[3])
        : "r"(a[0]), "r"(a[1]), "r"(a[2]), "r"(a[3]), "r"(b0), "r"(b1));
}

// C[M x N](f32) = A[M x K](f16, row-major) @ W[N x K]^T(f16, row-major) + bias[N]
template <int BM>
__global__ void __launch_bounds__(256) gemm_nt_kernel(
    const __half* __restrict__ A, const __half* __restrict__ W,
    const float* __restrict__ bias, float* __restrict__ C,
    int M, int N, int K) {
    constexpr int BN = 128, BK = 64, LDSH = BK + 8;
    constexpr int WM  = BM / 32;      // warps along M (2 or 1)
    constexpr int WN  = 8 / WM;       // warps along N (4 or 8)
    constexpr int WTN = BN / WN;      // 32 or 16
    constexpr int NTL = WTN / 8;      // n-tiles per warp (4 or 2)

    __shared__ __half A_s[BM * LDSH];
    __shared__ __half W_s[BN * LDSH];

    int tid = threadIdx.x;
    int warp = tid >> 5, lane = tid & 31;
    int wm = warp % WM, wn = warp / WM;
    int g = lane >> 2, ti = lane & 3;

    long rowA0 = (long)blockIdx.y * BM;
    long rowW0 = (long)blockIdx.x * BN;

    float acc[2][NTL][4];
#pragma unroll
    for (int mt = 0; mt < 2; mt++)
#pragma unroll
        for (int nt = 0; nt < NTL; nt++)
#pragma unroll
            for (int q = 0; q < 4; q++) acc[mt][nt][q] = 0.f;

    for (int k0 = 0; k0 < K; k0 += BK) {
        // load A tile (BM x 64 halves) as uint4
        for (int idx = tid; idx < BM * 8; idx += 256) {
            int row = idx >> 3, seg = idx & 7;
            uint4 val = make_uint4(0u, 0u, 0u, 0u);
            if (rowA0 + row < M)
                val = *(const uint4*)(A + (rowA0 + row) * (long)K + k0 + seg * 8);
            *(uint4*)(A_s + row * LDSH + seg * 8) = val;
        }
        // load W tile (128 x 64 halves)
        for (int idx = tid; idx < BN * 8; idx += 256) {
            int row = idx >> 3, seg = idx & 7;
            uint4 val = *(const uint4*)(W + (rowW0 + row) * (long)K + k0 + seg * 8);
            *(uint4*)(W_s + row * LDSH + seg * 8) = val;
        }
        __syncthreads();

#pragma unroll
        for (int kk = 0; kk < BK; kk += 16) {
            uint32_t afrag[2][4];
#pragma unroll
            for (int mt = 0; mt < 2; mt++) {
                int rbase = wm * 32 + mt * 16;
                afrag[mt][0] = *(const uint32_t*)(A_s + (rbase + g)     * LDSH + kk + 2 * ti);
                afrag[mt][1] = *(const uint32_t*)(A_s + (rbase + g + 8) * LDSH + kk + 2 * ti);
                afrag[mt][2] = *(const uint32_t*)(A_s + (rbase + g)     * LDSH + kk + 8 + 2 * ti);
                afrag[mt][3] = *(const uint32_t*)(A_s + (rbase + g + 8) * LDSH + kk + 8 + 2 * ti);
            }
#pragma unroll
            for (int nt = 0; nt < NTL; nt++) {
                int nb = wn * WTN + nt * 8 + g;
                uint32_t b0 = *(const uint32_t*)(W_s + nb * LDSH + kk + 2 * ti);
                uint32_t b1 = *(const uint32_t*)(W_s + nb * LDSH + kk + 8 + 2 * ti);
#pragma unroll
                for (int mt = 0; mt < 2; mt++) mma_m16n8k16(acc[mt][nt], afrag[mt], b0, b1);
            }
        }
        __syncthreads();
    }

    // epilogue: c0,c1 -> (g, 2ti..2ti+1); c2,c3 -> (g+8, ...)
#pragma unroll
    for (int mt = 0; mt < 2; mt++) {
        long row = rowA0 + wm * 32 + mt * 16 + g;
#pragma unroll
        for (int nt = 0; nt < NTL; nt++) {
            long col = rowW0 + wn * WTN + nt * 8 + 2 * ti;
            float bv0 = bias[col], bv1 = bias[col + 1];
            if (row < M) {
                C[row * N + col]     = acc[mt][nt][0] + bv0;
                C[row * N + col + 1] = acc[mt][nt][1] + bv1;
            }
            if (row + 8 < M) {
                C[(row + 8) * N + col]     = acc[mt][nt][2] + bv0;
                C[(row + 8) * N + col + 1] = acc[mt][nt][3] + bv1;
            }
        }
    }
}

// ------------------------- h init ----------------------------------------
__global__ void h_init_kernel(const float* __restrict__ h0) {
    int idx = blockIdx.x * blockDim.x + threadIdx.x;  // 32*4096
    float v = h0[idx & (NHH - 1)];
    gH[idx] = v;
    gHh[idx] = __float2half(v);
}

// ------------------------- GRU gate + state write ------------------------
__global__ void gate_kernel(float* __restrict__ d_out, int t) {
    int idx = blockIdx.x * blockDim.x + threadIdx.x;  // 131072
    int b = idx >> 12, n = idx & (NHH - 1);
    long gxr = ((long)(t * NB + b)) * NH3;
    const float* gh = gGh + (long)b * NH3;

    float xr = gGx[gxr + n];
    float xz = gGx[gxr + NHH + n];
    float xn = gGx[gxr + 2 * NHH + n];
    float hr = gh[n], hz = gh[NHH + n], hn = gh[2 * NHH + n];

    float r = 1.f / (1.f + expf(-(xr + hr)));
    float z = 1.f / (1.f + expf(-(xz + hz)));
    float nn = tanhf(xn + r * hn);
    float h = gH[idx];
    float hnew = (1.f - z) * nn + z * h;

    gH[idx] = hnew;
    gHh[idx] = __float2half(hnew);
    d_out[OUT_STATES + (long)b * (NHH * NTT) + (long)n * NTT + t] = hnew;
    if (t == NTT - 1) d_out[OUT_HENC + idx] = hnew;
}

// ------------------------- classifier ------------------------------------
__global__ void classifier_kernel(const float* __restrict__ w1, const float* __restrict__ b1,
                                  const float* __restrict__ w2, const float* __restrict__ b2,
                                  float* __restrict__ d_out) {
    __shared__ float hid[300];
    int b = blockIdx.x;
    int tid = threadIdx.x, warp = tid >> 5, lane = tid & 31;
    const float* hb = gH + (long)b * NHH;

    for (int j = warp; j < 300; j += 8) {
        float s = 0.f;
        for (int k = lane; k < NHH; k += 32) s += hb[k] * w1[(long)j * NHH + k];
#pragma unroll
        for (int off = 16; off; off >>= 1) s += __shfl_xor_sync(0xffffffffu, s, off);
        if (lane == 0) hid[j] = fmaxf(s + b1[j], 0.f);
    }
    __syncthreads();
    if (warp < 2) {
        float s = 0.f;
        for (int j = lane; j < 300; j += 32) s += hid[j] * w2[warp * 300 + j];
#pragma unroll
        for (int off = 16; off; off >>= 1) s += __shfl_xor_sync(0xffffffffu, s, off);
        if (lane == 0) d_out[OUT_CLS + b * 2 + warp] = s + b2[warp];
    }
}

// ------------------------- launch ----------------------------------------
extern "C" void kernel_launch(void* const* d_in, const int* in_sizes, int n_in,
                              void* d_out, int out_size) {
    const float* x      = (const float*)d_in[0];
    const float* adj    = (const float*)d_in[1];
    // d_in[2] = mask (unused by reference)
    const float* h0     = (const float*)d_in[3];
    const float* conv_w = (const float*)d_in[4];
    const float* conv_b = (const float*)d_in[5];
    const float* w_ih   = (const float*)d_in[6];
    const float* w_hh   = (const float*)d_in[7];
    const float* b_ih   = (const float*)d_in[8];
    const float* b_hh   = (const float*)d_in[9];
    const float* cls_w1 = (const float*)d_in[10];
    const float* cls_b1 = (const float*)d_in[11];
    const float* cls_w2 = (const float*)d_in[12];
    const float* cls_b2 = (const float*)d_in[13];
    float* out = (float*)d_out;

    // resolve scratch symbols (host-side, capture-safe, no allocations)
    void *pReprH, *pWih, *pWhh, *pGx, *pHh, *pGh;
    cudaGetSymbolAddress(&pReprH, gReprH);
    cudaGetSymbolAddress(&pWih, gWih);
    cudaGetSymbolAddress(&pWhh, gWhh);
    cudaGetSymbolAddress(&pGx, gGx);
    cudaGetSymbolAddress(&pHh, gHh);
    cudaGetSymbolAddress(&pGh, gGh);

    const int REPR_SMEM = (128 * 129 + 32 * 132 + 32 * 132 + 12 * 128) * 4;  // 105984 B
    cudaFuncSetAttribute(repr_kernel, cudaFuncAttributeMaxDynamicSharedMemorySize, REPR_SMEM);

    convert_weights_kernel<<<2048, 256>>>(w_ih, w_hh);
    support_kernel<<<1, 128>>>(adj);
    repr_kernel<<<NR, 256, REPR_SMEM>>>(x, conv_w, conv_b, out);
    h_init_kernel<<<512, 256>>>(h0);

    // gx for all timesteps: (3200 x 12288) = repr @ w_ih^T + b_ih
    gemm_nt_kernel<64><<<dim3(96, 50), 256>>>(
        (const __half*)pReprH, (const __half*)pWih, b_ih, (float*)pGx, NR, NH3, NHH);

    // sequential GRU
    for (int t = 0; t < NTT; t++) {
        gemm_nt_kernel<32><<<dim3(96, 1), 256>>>(
            (const __half*)pHh, (const __half*)pWhh, b_hh, (float*)pGh, NB, NH3, NHH);
        gate_kernel<<<512, 256>>>(out, t);
    }

    classifier_kernel<<<NB, 256>>>(cls_w1, cls_b1, cls_w2, cls_b2, out);
}

// round 4
// speedup vs baseline: 3.8583x; 3.8583x over previous
#include <cuda_runtime.h>
#include <cuda_fp16.h>
#include <cstdint>
#include <math.h>

// Problem dims
#define NB   32      // batch
#define NI   12      // input channels
#define NVV  128     // vertices
#define NHD  32      // conv hidden
#define NTT  100     // time steps
#define NHH  4096    // NH = V*H
#define NH3  12288   // 3*NH
#define NR   3200    // T*B rows

// d_out region offsets (floats)
static const long OUT_STATES = 13107200L;   // B*NH*T
static const long OUT_HENC   = 26214400L;   // + B*NH*T
static const long OUT_CLS    = 26345472L;   // + B*NH

// ------------------------- scratch (device globals, no allocs) -----------
__device__ float   gSupport[NVV * NVV];
__device__ __half  gReprH[(long)NR * NHH];       // 26 MB
__device__ __half  gWih[(long)NH3 * NHH];        // 100 MB
__device__ __half  gWhh[(long)NH3 * NHH];        // 100 MB
__device__ float   gGx[(long)NR * NH3];          // 157 MB
__device__ float   gH[NB * NHH];
__device__ __half  gHh[2][NB * NHH];             // double-buffered fp16 h

// ------------------------- cp.async helpers ------------------------------
__device__ __forceinline__ void cp_async16(void* smem, const void* gmem) {
    uint32_t s = (uint32_t)__cvta_generic_to_shared(smem);
    asm volatile("cp.async.cg.shared.global [%0], [%1], 16;\n" :: "r"(s), "l"(gmem));
}
__device__ __forceinline__ void cp_commit() {
    asm volatile("cp.async.commit_group;\n");
}
template <int N>
__device__ __forceinline__ void cp_wait() {
    asm volatile("cp.async.wait_group %0;\n" :: "n"(N));
}

// ------------------------- fp16 NT mma ----------------------------------
__device__ __forceinline__ void mma_m16n8k16(float* d, const uint32_t* a,
                                             uint32_t b0, uint32_t b1) {
    asm volatile(
        "mma.sync.aligned.m16n8k16.row.col.f32.f16.f16.f32 "
        "{%0,%1,%2,%3}, {%4,%5,%6,%7}, {%8,%9}, {%0,%1,%2,%3};\n"
        : "+f"(d[0]), "+f"(d[1]), "+f"(d[2]), "+f"(d[3])
        : "r"(a[0]), "r"(a[1]), "r"(a[2]), "r"(a[3]), "r"(b0), "r"(b1));
}

// ------------------------- weight conversion ------------------------------
__global__ void convert_weights_kernel(const float* __restrict__ wih,
                                       const float* __restrict__ whh) {
    long n = (long)NH3 * NHH;
    long stride = (long)gridDim.x * blockDim.x;
    for (long i = (long)blockIdx.x * blockDim.x + threadIdx.x; i < n; i += stride) {
        gWih[i] = __float2half(wih[i]);
        gWhh[i] = __float2half(whh[i]);
    }
}

// ------------------------- support = adj / (rowsum + 1e-6) ---------------
__global__ void support_kernel(const float* __restrict__ adj) {
    int w = threadIdx.x;  // 128 threads
    float s = 0.f;
    for (int v = 0; v < NVV; v++) s += adj[w * NVV + v];
    float inv = 1.f / (s + 1e-6f);
    for (int v = 0; v < NVV; v++) gSupport[w * NVV + v] = adj[w * NVV + v] * inv;
}

// ------------------------- repr: conv + 2x graph conv --------------------
__global__ void repr_kernel(const float* __restrict__ x,
                            const float* __restrict__ conv_w,
                            const float* __restrict__ conv_b,
                            float* __restrict__ d_out) {
    extern __shared__ float sm[];
    float* supT = sm;                  // [128][129]
    float* bufA = supT + 128 * 129;    // [32][132]
    float* bufB = bufA + 32 * 132;     // [32][132]
    float* xs   = bufB + 32 * 132;     // [12][128]

    int r = blockIdx.x;
    int t = r >> 5;
    int b = r & 31;
    int tid = threadIdx.x;

    for (int idx = tid; idx < NI * NVV; idx += 256) {
        int i = idx >> 7, v = idx & 127;
        xs[idx] = x[(((long)b * NI + i) * NVV + v) * NTT + t];
    }
    for (int idx = tid; idx < NVV * NVV; idx += 256) {
        int w = idx >> 7, v = idx & 127;
        supT[v * 129 + w] = gSupport[idx];
    }
    __syncthreads();

    for (int idx = tid; idx < NHD * NVV; idx += 256) {
        int h = idx >> 7, v = idx & 127;
        float a = conv_b[h];
#pragma unroll
        for (int i = 0; i < NI; i++) a += conv_w[h * NI + i] * xs[i * NVV + v];
        bufA[h * 132 + v] = a;
    }
    __syncthreads();

    int w0 = tid & 31;
    int h0 = tid >> 5;

    float acc1[4][4];
#pragma unroll
    for (int i = 0; i < 4; i++)
#pragma unroll
        for (int j = 0; j < 4; j++) acc1[i][j] = 0.f;
    for (int v = 0; v < NVV; v++) {
        float a[4], s[4];
#pragma unroll
        for (int i = 0; i < 4; i++) a[i] = bufA[(h0 + 8 * i) * 132 + v];
#pragma unroll
        for (int j = 0; j < 4; j++) s[j] = supT[v * 129 + w0 + 32 * j];
#pragma unroll
        for (int i = 0; i < 4; i++)
#pragma unroll
            for (int j = 0; j < 4; j++) acc1[i][j] += a[i] * s[j];
    }
    __syncthreads();
#pragma unroll
    for (int i = 0; i < 4; i++)
#pragma unroll
        for (int j = 0; j < 4; j++) bufB[(h0 + 8 * i) * 132 + w0 + 32 * j] = acc1[i][j];
    __syncthreads();

    float acc2[4][4];
#pragma unroll
    for (int i = 0; i < 4; i++)
#pragma unroll
        for (int j = 0; j < 4; j++) acc2[i][j] = 0.f;
    for (int v = 0; v < NVV; v++) {
        float a[4], s[4];
#pragma unroll
        for (int i = 0; i < 4; i++) a[i] = bufB[(h0 + 8 * i) * 132 + v];
#pragma unroll
        for (int j = 0; j < 4; j++) s[j] = supT[v * 129 + w0 + 32 * j];
#pragma unroll
        for (int i = 0; i < 4; i++)
#pragma unroll
            for (int j = 0; j < 4; j++) acc2[i][j] += a[i] * s[j];
    }

#pragma unroll
    for (int i = 0; i < 4; i++) {
#pragma unroll
        for (int j = 0; j < 4; j++) {
            int h = h0 + 8 * i, w = w0 + 32 * j;
            int n = h * NVV + w;
            float val = acc2[i][j];
            d_out[(long)b * (NHH * NTT) + (long)n * NTT + t] = val;
            gReprH[(long)r * NHH + n] = __float2half(val);
        }
    }
}

// ------------------------- pipelined gx GEMM -----------------------------
// C[3200 x 12288](f32) = A[3200 x 4096](f16) @ W[12288 x 4096]^T(f16) + bias
// Exact-fit: grid (96, 25), BM=128, BN=128, BK=64, 3-stage cp.async.
__global__ void __launch_bounds__(256) gemm_gx_kernel(const float* __restrict__ bias) {
    constexpr int BM = 128, BN = 128, BK = 64, ST = 3, LD = 72;
    extern __shared__ __half smh[];
    __half* As = smh;                       // ST * BM * LD
    __half* Ws = smh + ST * BM * LD;        // ST * BN * LD

    int tid = threadIdx.x;
    int warp = tid >> 5, lane = tid & 31;
    int g = lane >> 2, ti = lane & 3;
    int wm = warp & 1, wn = warp >> 1;      // 2 x 4 warp grid, warp tile 64x32

    long rowA0 = (long)blockIdx.y * BM;
    long rowW0 = (long)blockIdx.x * BN;

    const __half* A = gReprH;
    const __half* W = gWih;

    int ldrow = tid >> 3, ldseg = tid & 7;

    // prologue: stages 0,1
#pragma unroll
    for (int s = 0; s < ST - 1; s++) {
        int k0 = s * BK;
#pragma unroll
        for (int i = 0; i < 4; i++) {
            int row = ldrow + i * 32;
            cp_async16(As + (s * BM + row) * LD + ldseg * 8,
                       A + (rowA0 + row) * (long)NHH + k0 + ldseg * 8);
        }
#pragma unroll
        for (int i = 0; i < 4; i++) {
            int row = ldrow + i * 32;
            cp_async16(Ws + (s * BN + row) * LD + ldseg * 8,
                       W + (rowW0 + row) * (long)NHH + k0 + ldseg * 8);
        }
        cp_commit();
    }

    float acc[4][4][4];
#pragma unroll
    for (int mt = 0; mt < 4; mt++)
#pragma unroll
        for (int nt = 0; nt < 4; nt++)
#pragma unroll
            for (int q = 0; q < 4; q++) acc[mt][nt][q] = 0.f;

    const int KT = NHH / BK;  // 64
    for (int kt = 0; kt < KT; kt++) {
        cp_wait<ST - 2>();
        __syncthreads();
        if (kt + ST - 1 < KT) {
            int s = (kt + ST - 1) % ST;
            int k0 = (kt + ST - 1) * BK;
#pragma unroll
            for (int i = 0; i < 4; i++) {
                int row = ldrow + i * 32;
                cp_async16(As + (s * BM + row) * LD + ldseg * 8,
                           A + (rowA0 + row) * (long)NHH + k0 + ldseg * 8);
            }
#pragma unroll
            for (int i = 0; i < 4; i++) {
                int row = ldrow + i * 32;
                cp_async16(Ws + (s * BN + row) * LD + ldseg * 8,
                           W + (rowW0 + row) * (long)NHH + k0 + ldseg * 8);
            }
        }
        // Commit EVERY iteration (possibly empty) so wait_group counts stay
        // aligned in the pipeline tail. Without this, the final K-chunk races
        // against its own cp.async (round-3 bug: states rel_err 8e-3).
        cp_commit();

        const __half* Ab = As + (kt % ST) * BM * LD;
        const __half* Wb = Ws + (kt % ST) * BN * LD;

#pragma unroll
        for (int kk = 0; kk < BK; kk += 16) {
            uint32_t af[4][4];
#pragma unroll
            for (int mt = 0; mt < 4; mt++) {
                int rbase = wm * 64 + mt * 16;
                af[mt][0] = *(const uint32_t*)(Ab + (rbase + g)     * LD + kk + 2 * ti);
                af[mt][1] = *(const uint32_t*)(Ab + (rbase + g + 8) * LD + kk + 2 * ti);
                af[mt][2] = *(const uint32_t*)(Ab + (rbase + g)     * LD + kk + 8 + 2 * ti);
                af[mt][3] = *(const uint32_t*)(Ab + (rbase + g + 8) * LD + kk + 8 + 2 * ti);
            }
#pragma unroll
            for (int nt = 0; nt < 4; nt++) {
                int nb = wn * 32 + nt * 8 + g;
                uint32_t b0 = *(const uint32_t*)(Wb + nb * LD + kk + 2 * ti);
                uint32_t b1 = *(const uint32_t*)(Wb + nb * LD + kk + 8 + 2 * ti);
#pragma unroll
                for (int mt = 0; mt < 4; mt++) mma_m16n8k16(acc[mt][nt], af[mt], b0, b1);
            }
        }
    }

    // epilogue (exact fit, no predicates)
    float* C = gGx;
#pragma unroll
    for (int mt = 0; mt < 4; mt++) {
        long row = rowA0 + wm * 64 + mt * 16 + g;
#pragma unroll
        for (int nt = 0; nt < 4; nt++) {
            long col = rowW0 + wn * 32 + nt * 8 + 2 * ti;
            float bv0 = bias[col], bv1 = bias[col + 1];
            C[row * NH3 + col]           = acc[mt][nt][0] + bv0;
            C[row * NH3 + col + 1]       = acc[mt][nt][1] + bv1;
            C[(row + 8) * NH3 + col]     = acc[mt][nt][2] + bv0;
            C[(row + 8) * NH3 + col + 1] = acc[mt][nt][3] + bv1;
        }
    }
}

// ------------------------- h init ----------------------------------------
__global__ void h_init_kernel(const float* __restrict__ h0) {
    int idx = blockIdx.x * blockDim.x + threadIdx.x;  // 32*4096
    float v = h0[idx & (NHH - 1)];
    gH[idx] = v;
    gHh[0][idx] = __float2half(v);
}

// ------------------------- fused GRU step --------------------------------
// Block j covers hidden cols [n0, n0+32) for ALL 3 gates (96 W rows).
__global__ void __launch_bounds__(256) gru_step_kernel(
    const __half* __restrict__ Ain,   // gHh[t&1]
    __half* __restrict__ Aout,        // gHh[(t+1)&1]
    const float* __restrict__ b_hh,
    float* __restrict__ d_out, int t) {
    constexpr int BK = 64, ST = 3, LD = 72, WR = 96, AR = 32;
    extern __shared__ char smraw[];
    __half* As   = (__half*)smraw;                // ST * 32 * LD
    __half* Ws   = As + ST * AR * LD;             // ST * 96 * LD
    float*  gh_s = (float*)(Ws + ST * WR * LD);   // 32 * 100

    int tid = threadIdx.x;
    int warp = tid >> 5, lane = tid & 31;
    int g = lane >> 2, ti = lane & 3;
    int wm = warp & 1, wn = warp >> 1;            // 2 x 4, each warp: 16 x 24
    int n0 = blockIdx.x * 32;

    int ldrow = tid >> 3, ldseg = tid & 7;

    // prologue
#pragma unroll
    for (int s = 0; s < ST - 1; s++) {
        int k0 = s * BK;
        cp_async16(As + (s * AR + ldrow) * LD + ldseg * 8,
                   Ain + ldrow * NHH + k0 + ldseg * 8);
#pragma unroll
        for (int i = 0; i < 3; i++) {
            int lr = ldrow + i * 32;
            long wr = (long)(lr >> 5) * NHH + n0 + (lr & 31);
            cp_async16(Ws + (s * WR + lr) * LD + ldseg * 8,
                       gWhh + wr * NHH + k0 + ldseg * 8);
        }
        cp_commit();
    }

    float acc[3][4];
#pragma unroll
    for (int nt = 0; nt < 3; nt++)
#pragma unroll
        for (int q = 0; q < 4; q++) acc[nt][q] = 0.f;

    const int KT = NHH / BK;  // 64
    for (int kt = 0; kt < KT; kt++) {
        cp_wait<ST - 2>();
        __syncthreads();
        if (kt + ST - 1 < KT) {
            int s = (kt + ST - 1) % ST;
            int k0 = (kt + ST - 1) * BK;
            cp_async16(As + (s * AR + ldrow) * LD + ldseg * 8,
                       Ain + ldrow * NHH + k0 + ldseg * 8);
#pragma unroll
            for (int i = 0; i < 3; i++) {
                int lr = ldrow + i * 32;
                long wr = (long)(lr >> 5) * NHH + n0 + (lr & 31);
                cp_async16(Ws + (s * WR + lr) * LD + ldseg * 8,
                           gWhh + wr * NHH + k0 + ldseg * 8);
            }
        }
        // Commit every iteration (tail-alignment fix, see gemm_gx_kernel).
        cp_commit();

        const __half* Ab = As + (kt % ST) * AR * LD;
        const __half* Wb = Ws + (kt % ST) * WR * LD;

#pragma unroll
        for (int kk = 0; kk < BK; kk += 16) {
            uint32_t af[4];
            int rbase = wm * 16;
            af[0] = *(const uint32_t*)(Ab + (rbase + g)     * LD + kk + 2 * ti);
            af[1] = *(const uint32_t*)(Ab + (rbase + g + 8) * LD + kk + 2 * ti);
            af[2] = *(const uint32_t*)(Ab + (rbase + g)     * LD + kk + 8 + 2 * ti);
            af[3] = *(const uint32_t*)(Ab + (rbase + g + 8) * LD + kk + 8 + 2 * ti);
#pragma unroll
            for (int nt = 0; nt < 3; nt++) {
                int nb = (wn * 3 + nt) * 8 + g;
                uint32_t b0 = *(const uint32_t*)(Wb + nb * LD + kk + 2 * ti);
                uint32_t b1 = *(const uint32_t*)(Wb + nb * LD + kk + 8 + 2 * ti);
                mma_m16n8k16(acc[nt], af, b0, b1);
            }
        }
    }

    // write gh to smem [batch m][col c], stride 100
#pragma unroll
    for (int nt = 0; nt < 3; nt++) {
        int c = (wn * 3 + nt) * 8 + 2 * ti;
        int m = wm * 16 + g;
        gh_s[m * 100 + c]           = acc[nt][0];
        gh_s[m * 100 + c + 1]       = acc[nt][1];
        gh_s[(m + 8) * 100 + c]     = acc[nt][2];
        gh_s[(m + 8) * 100 + c + 1] = acc[nt][3];
    }
    __syncthreads();

    // gate math: 32 batches x 32 cols = 1024 elems, 4 per thread
#pragma unroll
    for (int i = 0; i < 4; i++) {
        int idx = tid + i * 256;
        int b = idx >> 5, nl = idx & 31;
        int n = n0 + nl;

        float hr = gh_s[b * 100 + nl]      + b_hh[n];
        float hz = gh_s[b * 100 + 32 + nl] + b_hh[NHH + n];
        float hn = gh_s[b * 100 + 64 + nl] + b_hh[2 * NHH + n];

        long gxr = ((long)(t * NB + b)) * NH3;
        float xr = gGx[gxr + n];
        float xz = gGx[gxr + NHH + n];
        float xn = gGx[gxr + 2 * NHH + n];

        float r = 1.f / (1.f + expf(-(xr + hr)));
        float z = 1.f / (1.f + expf(-(xz + hz)));
        float nn = tanhf(xn + r * hn);
        float h = gH[b * NHH + n];
        float hnew = (1.f - z) * nn + z * h;

        gH[b * NHH + n] = hnew;
        Aout[b * NHH + n] = __float2half(hnew);
        d_out[OUT_STATES + (long)b * (NHH * NTT) + (long)n * NTT + t] = hnew;
        if (t == NTT - 1) d_out[OUT_HENC + b * NHH + n] = hnew;
    }
}

// ------------------------- classifier ------------------------------------
__global__ void classifier_kernel(const float* __restrict__ w1, const float* __restrict__ b1,
                                  const float* __restrict__ w2, const float* __restrict__ b2,
                                  float* __restrict__ d_out) {
    __shared__ float hid[300];
    int b = blockIdx.x;
    int tid = threadIdx.x, warp = tid >> 5, lane = tid & 31;
    const float* hb = gH + (long)b * NHH;

    for (int j = warp; j < 300; j += 8) {
        float s = 0.f;
        for (int k = lane; k < NHH; k += 32) s += hb[k] * w1[(long)j * NHH + k];
#pragma unroll
        for (int off = 16; off; off >>= 1) s += __shfl_xor_sync(0xffffffffu, s, off);
        if (lane == 0) hid[j] = fmaxf(s + b1[j], 0.f);
    }
    __syncthreads();
    if (warp < 2) {
        float s = 0.f;
        for (int j = lane; j < 300; j += 32) s += hid[j] * w2[warp * 300 + j];
#pragma unroll
        for (int off = 16; off; off >>= 1) s += __shfl_xor_sync(0xffffffffu, s, off);
        if (lane == 0) d_out[OUT_CLS + b * 2 + warp] = s + b2[warp];
    }
}

// ------------------------- launch ----------------------------------------
extern "C" void kernel_launch(void* const* d_in, const int* in_sizes, int n_in,
                              void* d_out, int out_size) {
    const float* x      = (const float*)d_in[0];
    const float* adj    = (const float*)d_in[1];
    const float* h0     = (const float*)d_in[3];
    const float* conv_w = (const float*)d_in[4];
    const float* conv_b = (const float*)d_in[5];
    const float* w_ih   = (const float*)d_in[6];
    const float* w_hh   = (const float*)d_in[7];
    const float* b_ih   = (const float*)d_in[8];
    const float* b_hh   = (const float*)d_in[9];
    const float* cls_w1 = (const float*)d_in[10];
    const float* cls_b1 = (const float*)d_in[11];
    const float* cls_w2 = (const float*)d_in[12];
    const float* cls_b2 = (const float*)d_in[13];
    float* out = (float*)d_out;

    void* pHh;
    cudaGetSymbolAddress(&pHh, gHh);
    __half* hbuf0 = (__half*)pHh;
    __half* hbuf1 = hbuf0 + NB * NHH;

    const int REPR_SMEM = (128 * 129 + 32 * 132 + 32 * 132 + 12 * 128) * 4;  // 105984
    const int GX_SMEM   = 3 * (128 + 128) * 72 * 2;                          // 110592
    const int ST_SMEM   = 3 * (32 + 96) * 72 * 2 + 32 * 100 * 4;             // 68096
    cudaFuncSetAttribute(repr_kernel, cudaFuncAttributeMaxDynamicSharedMemorySize, REPR_SMEM);
    cudaFuncSetAttribute(gemm_gx_kernel, cudaFuncAttributeMaxDynamicSharedMemorySize, GX_SMEM);
    cudaFuncSetAttribute(gru_step_kernel, cudaFuncAttributeMaxDynamicSharedMemorySize, ST_SMEM);

    convert_weights_kernel<<<2048, 256>>>(w_ih, w_hh);
    support_kernel<<<1, 128>>>(adj);
    repr_kernel<<<NR, 256, REPR_SMEM>>>(x, conv_w, conv_b, out);
    h_init_kernel<<<512, 256>>>(h0);

    gemm_gx_kernel<<<dim3(96, 25), 256, GX_SMEM>>>(b_ih);

    for (int t = 0; t < NTT; t++) {
        const __half* ain = (t & 1) ? hbuf1 : hbuf0;
        __half* aout      = (t & 1) ? hbuf0 : hbuf1;
        gru_step_kernel<<<128, 256, ST_SMEM>>>(ain, aout, b_hh, out, t);
    }

    classifier_kernel<<<NB, 256>>>(cls_w1, cls_b1, cls_w2, cls_b2, out);
}

// round 5
// speedup vs baseline: 4.4896x; 1.1636x over previous
#include <cuda_runtime.h>
#include <cuda_fp16.h>
#include <cstdint>
#include <math.h>

// Problem dims
#define NB   32      // batch
#define NI   12      // input channels
#define NVV  128     // vertices
#define NHD  32      // conv hidden
#define NTT  100     // time steps
#define NHH  4096    // NH = V*H
#define NH3  12288   // 3*NH
#define NR   3200    // T*B rows
#define NBLK 128     // persistent recurrence blocks (<=148 SMs: co-resident)

// d_out region offsets (floats)
static const long OUT_STATES = 13107200L;   // B*NH*T
static const long OUT_HENC   = 26214400L;   // + B*NH*T
static const long OUT_CLS    = 26345472L;   // + B*NH

// ------------------------- scratch (device globals, no allocs) -----------
__device__ float    gSupport[NVV * NVV];
__device__ __half   gReprH[(long)NR * NHH];      // 26 MB
__device__ __half   gWih[(long)NH3 * NHH];       // 100 MB
__device__ __half   gWhh[(long)NH3 * NHH];       // 100 MB
__device__ float    gGx[(long)NR * NH3];         // 157 MB
__device__ __half   gHh[2][NB * NHH];            // double-buffered fp16 h
__device__ unsigned gBarCnt;                      // grid barrier arrive count
__device__ unsigned gBarPhase;                    // grid barrier phase (monotonic)

// ------------------------- cp.async helpers ------------------------------
__device__ __forceinline__ void cp_async16(void* smem, const void* gmem) {
    uint32_t s = (uint32_t)__cvta_generic_to_shared(smem);
    asm volatile("cp.async.cg.shared.global [%0], [%1], 16;\n" :: "r"(s), "l"(gmem));
}
__device__ __forceinline__ void cp_commit() {
    asm volatile("cp.async.commit_group;\n");
}
template <int N>
__device__ __forceinline__ void cp_wait() {
    asm volatile("cp.async.wait_group %0;\n" :: "n"(N));
}

// ------------------------- fp16 NT mma ----------------------------------
__device__ __forceinline__ void mma_m16n8k16(float* d, const uint32_t* a,
                                             uint32_t b0, uint32_t b1) {
    asm volatile(
        "mma.sync.aligned.m16n8k16.row.col.f32.f16.f16.f32 "
        "{%0,%1,%2,%3}, {%4,%5,%6,%7}, {%8,%9}, {%0,%1,%2,%3};\n"
        : "+f"(d[0]), "+f"(d[1]), "+f"(d[2]), "+f"(d[3])
        : "r"(a[0]), "r"(a[1]), "r"(a[2]), "r"(a[3]), "r"(b0), "r"(b1));
}

// ------------------------- weight conversion (vectorized) -----------------
__global__ void convert_weights_kernel(const float4* __restrict__ wih4,
                                       const float4* __restrict__ whh4) {
    long n4 = (long)NH3 * NHH / 4;
    long stride = (long)gridDim.x * blockDim.x;
    __half2* wih_o = (__half2*)gWih;
    __half2* whh_o = (__half2*)gWhh;
    for (long i = (long)blockIdx.x * blockDim.x + threadIdx.x; i < n4; i += stride) {
        float4 a = wih4[i];
        wih_o[2 * i]     = __floats2half2_rn(a.x, a.y);
        wih_o[2 * i + 1] = __floats2half2_rn(a.z, a.w);
        float4 b = whh4[i];
        whh_o[2 * i]     = __floats2half2_rn(b.x, b.y);
        whh_o[2 * i + 1] = __floats2half2_rn(b.z, b.w);
    }
}

// ------------------------- support = adj / (rowsum + 1e-6) ---------------
__global__ void support_kernel(const float* __restrict__ adj) {
    int w = threadIdx.x;  // 128 threads
    float s = 0.f;
    for (int v = 0; v < NVV; v++) s += adj[w * NVV + v];
    float inv = 1.f / (s + 1e-6f);
    for (int v = 0; v < NVV; v++) gSupport[w * NVV + v] = adj[w * NVV + v] * inv;
}

// ------------------------- repr: conv + 2x graph conv --------------------
__global__ void repr_kernel(const float* __restrict__ x,
                            const float* __restrict__ conv_w,
                            const float* __restrict__ conv_b,
                            float* __restrict__ d_out) {
    extern __shared__ float sm[];
    float* supT = sm;                  // [128][129]
    float* bufA = supT + 128 * 129;    // [32][132]
    float* bufB = bufA + 32 * 132;     // [32][132]
    float* xs   = bufB + 32 * 132;     // [12][128]

    int r = blockIdx.x;
    int t = r >> 5;
    int b = r & 31;
    int tid = threadIdx.x;

    for (int idx = tid; idx < NI * NVV; idx += 256) {
        int i = idx >> 7, v = idx & 127;
        xs[idx] = x[(((long)b * NI + i) * NVV + v) * NTT + t];
    }
    for (int idx = tid; idx < NVV * NVV; idx += 256) {
        int w = idx >> 7, v = idx & 127;
        supT[v * 129 + w] = gSupport[idx];
    }
    __syncthreads();

    for (int idx = tid; idx < NHD * NVV; idx += 256) {
        int h = idx >> 7, v = idx & 127;
        float a = conv_b[h];
#pragma unroll
        for (int i = 0; i < NI; i++) a += conv_w[h * NI + i] * xs[i * NVV + v];
        bufA[h * 132 + v] = a;
    }
    __syncthreads();

    int w0 = tid & 31;
    int h0 = tid >> 5;

    float acc1[4][4];
#pragma unroll
    for (int i = 0; i < 4; i++)
#pragma unroll
        for (int j = 0; j < 4; j++) acc1[i][j] = 0.f;
    for (int v = 0; v < NVV; v++) {
        float a[4], s[4];
#pragma unroll
        for (int i = 0; i < 4; i++) a[i] = bufA[(h0 + 8 * i) * 132 + v];
#pragma unroll
        for (int j = 0; j < 4; j++) s[j] = supT[v * 129 + w0 + 32 * j];
#pragma unroll
        for (int i = 0; i < 4; i++)
#pragma unroll
            for (int j = 0; j < 4; j++) acc1[i][j] += a[i] * s[j];
    }
    __syncthreads();
#pragma unroll
    for (int i = 0; i < 4; i++)
#pragma unroll
        for (int j = 0; j < 4; j++) bufB[(h0 + 8 * i) * 132 + w0 + 32 * j] = acc1[i][j];
    __syncthreads();

    float acc2[4][4];
#pragma unroll
    for (int i = 0; i < 4; i++)
#pragma unroll
        for (int j = 0; j < 4; j++) acc2[i][j] = 0.f;
    for (int v = 0; v < NVV; v++) {
        float a[4], s[4];
#pragma unroll
        for (int i = 0; i < 4; i++) a[i] = bufB[(h0 + 8 * i) * 132 + v];
#pragma unroll
        for (int j = 0; j < 4; j++) s[j] = supT[v * 129 + w0 + 32 * j];
#pragma unroll
        for (int i = 0; i < 4; i++)
#pragma unroll
            for (int j = 0; j < 4; j++) acc2[i][j] += a[i] * s[j];
    }

#pragma unroll
    for (int i = 0; i < 4; i++) {
#pragma unroll
        for (int j = 0; j < 4; j++) {
            int h = h0 + 8 * i, w = w0 + 32 * j;
            int n = h * NVV + w;
            float val = acc2[i][j];
            d_out[(long)b * (NHH * NTT) + (long)n * NTT + t] = val;
            gReprH[(long)r * NHH + n] = __float2half(val);
        }
    }
}

// ------------------------- pipelined gx GEMM -----------------------------
// C[3200 x 12288](f32) = A[3200 x 4096](f16) @ W[12288 x 4096]^T(f16) + bias
__global__ void __launch_bounds__(256) gemm_gx_kernel(const float* __restrict__ bias) {
    constexpr int BM = 128, BN = 128, BK = 64, ST = 3, LD = 72;
    extern __shared__ __half smh[];
    __half* As = smh;
    __half* Ws = smh + ST * BM * LD;

    int tid = threadIdx.x;
    int warp = tid >> 5, lane = tid & 31;
    int g = lane >> 2, ti = lane & 3;
    int wm = warp & 1, wn = warp >> 1;

    long rowA0 = (long)blockIdx.y * BM;
    long rowW0 = (long)blockIdx.x * BN;

    const __half* A = gReprH;
    const __half* W = gWih;

    int ldrow = tid >> 3, ldseg = tid & 7;

#pragma unroll
    for (int s = 0; s < ST - 1; s++) {
        int k0 = s * BK;
#pragma unroll
        for (int i = 0; i < 4; i++) {
            int row = ldrow + i * 32;
            cp_async16(As + (s * BM + row) * LD + ldseg * 8,
                       A + (rowA0 + row) * (long)NHH + k0 + ldseg * 8);
        }
#pragma unroll
        for (int i = 0; i < 4; i++) {
            int row = ldrow + i * 32;
            cp_async16(Ws + (s * BN + row) * LD + ldseg * 8,
                       W + (rowW0 + row) * (long)NHH + k0 + ldseg * 8);
        }
        cp_commit();
    }

    float acc[4][4][4];
#pragma unroll
    for (int mt = 0; mt < 4; mt++)
#pragma unroll
        for (int nt = 0; nt < 4; nt++)
#pragma unroll
            for (int q = 0; q < 4; q++) acc[mt][nt][q] = 0.f;

    const int KT = NHH / BK;
    for (int kt = 0; kt < KT; kt++) {
        cp_wait<ST - 2>();
        __syncthreads();
        if (kt + ST - 1 < KT) {
            int s = (kt + ST - 1) % ST;
            int k0 = (kt + ST - 1) * BK;
#pragma unroll
            for (int i = 0; i < 4; i++) {
                int row = ldrow + i * 32;
                cp_async16(As + (s * BM + row) * LD + ldseg * 8,
                           A + (rowA0 + row) * (long)NHH + k0 + ldseg * 8);
            }
#pragma unroll
            for (int i = 0; i < 4; i++) {
                int row = ldrow + i * 32;
                cp_async16(Ws + (s * BN + row) * LD + ldseg * 8,
                           W + (rowW0 + row) * (long)NHH + k0 + ldseg * 8);
            }
        }
        cp_commit();  // every iter (tail alignment)

        const __half* Ab = As + (kt % ST) * BM * LD;
        const __half* Wb = Ws + (kt % ST) * BN * LD;

#pragma unroll
        for (int kk = 0; kk < BK; kk += 16) {
            uint32_t af[4][4];
#pragma unroll
            for (int mt = 0; mt < 4; mt++) {
                int rbase = wm * 64 + mt * 16;
                af[mt][0] = *(const uint32_t*)(Ab + (rbase + g)     * LD + kk + 2 * ti);
                af[mt][1] = *(const uint32_t*)(Ab + (rbase + g + 8) * LD + kk + 2 * ti);
                af[mt][2] = *(const uint32_t*)(Ab + (rbase + g)     * LD + kk + 8 + 2 * ti);
                af[mt][3] = *(const uint32_t*)(Ab + (rbase + g + 8) * LD + kk + 8 + 2 * ti);
            }
#pragma unroll
            for (int nt = 0; nt < 4; nt++) {
                int nb = wn * 32 + nt * 8 + g;
                uint32_t b0 = *(const uint32_t*)(Wb + nb * LD + kk + 2 * ti);
                uint32_t b1 = *(const uint32_t*)(Wb + nb * LD + kk + 8 + 2 * ti);
#pragma unroll
                for (int mt = 0; mt < 4; mt++) mma_m16n8k16(acc[mt][nt], af[mt], b0, b1);
            }
        }
    }

    float* C = gGx;
#pragma unroll
    for (int mt = 0; mt < 4; mt++) {
        long row = rowA0 + wm * 64 + mt * 16 + g;
#pragma unroll
        for (int nt = 0; nt < 4; nt++) {
            long col = rowW0 + wn * 32 + nt * 8 + 2 * ti;
            float bv0 = bias[col], bv1 = bias[col + 1];
            C[row * NH3 + col]           = acc[mt][nt][0] + bv0;
            C[row * NH3 + col + 1]       = acc[mt][nt][1] + bv1;
            C[(row + 8) * NH3 + col]     = acc[mt][nt][2] + bv0;
            C[(row + 8) * NH3 + col + 1] = acc[mt][nt][3] + bv1;
        }
    }
}

// ------------------------- h init (fp16 buffer only) ---------------------
__global__ void h_init_kernel(const float* __restrict__ h0) {
    int idx = blockIdx.x * blockDim.x + threadIdx.x;  // 32*4096
    gHh[0][idx] = __float2half(h0[idx & (NHH - 1)]);
}

// ------------------------- persistent GRU --------------------------------
// ONE launch for all 100 timesteps. 128 blocks (co-resident on 148 SMs),
// block j owns hidden cols [32j, 32j+32) for all 3 gates; h kept in regs.
__global__ void __launch_bounds__(256) gru_persistent_kernel(
    const float* __restrict__ h0,
    const float* __restrict__ b_hh,
    float* __restrict__ d_out) {
    constexpr int BK = 64, ST = 4, LD = 72, WR = 96, AR = 32;
    extern __shared__ char smraw[];
    __half* As   = (__half*)smraw;                // ST * 32 * LD
    __half* Ws   = As + ST * AR * LD;             // ST * 96 * LD
    float*  gh_s = (float*)(Ws + ST * WR * LD);   // 32 * 100

    int tid = threadIdx.x;
    int warp = tid >> 5, lane = tid & 31;
    int g = lane >> 2, ti = lane & 3;
    int wm = warp & 1, wn = warp >> 1;            // 2 x 4, warp: 16 x 24
    int n0 = blockIdx.x * 32;

    int ldrow = tid >> 3, ldseg = tid & 7;

    // fixed W row pointers (3 per thread)
    const __half* wptr[3];
#pragma unroll
    for (int i = 0; i < 3; i++) {
        int lr = ldrow + i * 32;
        long wr = (long)(lr >> 5) * NHH + n0 + (lr & 31);
        wptr[i] = gWhh + wr * (long)NHH + ldseg * 8;
    }

    // per-thread gate state: idx = tid + i*256 -> (b = idx>>5, nl = idx&31)
    float hreg[4], bhr[4], bhz[4], bhn[4];
#pragma unroll
    for (int i = 0; i < 4; i++) {
        int idx = tid + i * 256;
        int n = n0 + (idx & 31);
        hreg[i] = h0[n];
        bhr[i] = b_hh[n];
        bhz[i] = b_hh[NHH + n];
        bhn[i] = b_hh[2 * NHH + n];
    }

    // barrier base phase (read BEFORE first arrival -> replay-safe)
    unsigned barBase = *(volatile unsigned*)&gBarPhase;

    for (int t = 0; t < NTT; t++) {
        const __half* Ain = gHh[t & 1];
        __half* Aout = gHh[(t + 1) & 1];
        const __half* aptr = Ain + ldrow * NHH + ldseg * 8;

        cp_wait<0>();  // drain any stale empty groups; clean per-step counting

        // prologue: stages 0..ST-2
#pragma unroll
        for (int s = 0; s < ST - 1; s++) {
            int k0 = s * BK;
            cp_async16(As + (s * AR + ldrow) * LD + ldseg * 8, aptr + k0);
#pragma unroll
            for (int i = 0; i < 3; i++) {
                int lr = ldrow + i * 32;
                cp_async16(Ws + (s * WR + lr) * LD + ldseg * 8, wptr[i] + k0);
            }
            cp_commit();
        }

        float acc[3][4];
#pragma unroll
        for (int nt = 0; nt < 3; nt++)
#pragma unroll
            for (int q = 0; q < 4; q++) acc[nt][q] = 0.f;

        const int KT = NHH / BK;  // 64
        for (int kt = 0; kt < KT; kt++) {
            cp_wait<ST - 2>();
            __syncthreads();
            if (kt + ST - 1 < KT) {
                int s = (kt + ST - 1) % ST;
                int k0 = (kt + ST - 1) * BK;
                cp_async16(As + (s * AR + ldrow) * LD + ldseg * 8, aptr + k0);
#pragma unroll
                for (int i = 0; i < 3; i++) {
                    int lr = ldrow + i * 32;
                    cp_async16(Ws + (s * WR + lr) * LD + ldseg * 8, wptr[i] + k0);
                }
            }
            cp_commit();  // every iter (tail alignment)

            const __half* Ab = As + (kt % ST) * AR * LD;
            const __half* Wb = Ws + (kt % ST) * WR * LD;

#pragma unroll
            for (int kk = 0; kk < BK; kk += 16) {
                uint32_t af[4];
                int rbase = wm * 16;
                af[0] = *(const uint32_t*)(Ab + (rbase + g)     * LD + kk + 2 * ti);
                af[1] = *(const uint32_t*)(Ab + (rbase + g + 8) * LD + kk + 2 * ti);
                af[2] = *(const uint32_t*)(Ab + (rbase + g)     * LD + kk + 8 + 2 * ti);
                af[3] = *(const uint32_t*)(Ab + (rbase + g + 8) * LD + kk + 8 + 2 * ti);
#pragma unroll
                for (int nt = 0; nt < 3; nt++) {
                    int nb = (wn * 3 + nt) * 8 + g;
                    uint32_t b0 = *(const uint32_t*)(Wb + nb * LD + kk + 2 * ti);
                    uint32_t b1 = *(const uint32_t*)(Wb + nb * LD + kk + 8 + 2 * ti);
                    mma_m16n8k16(acc[nt], af, b0, b1);
                }
            }
        }

        // gh -> smem [batch m][col c]
#pragma unroll
        for (int nt = 0; nt < 3; nt++) {
            int c = (wn * 3 + nt) * 8 + 2 * ti;
            int m = wm * 16 + g;
            gh_s[m * 100 + c]           = acc[nt][0];
            gh_s[m * 100 + c + 1]       = acc[nt][1];
            gh_s[(m + 8) * 100 + c]     = acc[nt][2];
            gh_s[(m + 8) * 100 + c + 1] = acc[nt][3];
        }
        __syncthreads();

        // gate math (h in registers)
#pragma unroll
        for (int i = 0; i < 4; i++) {
            int idx = tid + i * 256;
            int b = idx >> 5, nl = idx & 31;
            int n = n0 + nl;

            float hr = gh_s[b * 100 + nl]      + bhr[i];
            float hz = gh_s[b * 100 + 32 + nl] + bhz[i];
            float hn = gh_s[b * 100 + 64 + nl] + bhn[i];

            long gxr = ((long)(t * NB + b)) * NH3;
            float xr = gGx[gxr + n];
            float xz = gGx[gxr + NHH + n];
            float xn = gGx[gxr + 2 * NHH + n];

            float r = 1.f / (1.f + expf(-(xr + hr)));
            float z = 1.f / (1.f + expf(-(xz + hz)));
            float nn = tanhf(xn + r * hn);
            float hnew = (1.f - z) * nn + z * hreg[i];
            hreg[i] = hnew;

            Aout[b * NHH + n] = __float2half(hnew);
            d_out[OUT_STATES + (long)b * (NHH * NTT) + (long)n * NTT + t] = hnew;
            if (t == NTT - 1) d_out[OUT_HENC + b * NHH + n] = hnew;
        }

        // ---- grid barrier (sense via monotonic phase; replay-safe) ----
        __syncthreads();
        if (tid == 0) {
            __threadfence();
            unsigned arrived = atomicAdd(&gBarCnt, 1u);
            unsigned target = barBase + (unsigned)(t + 1);
            if (arrived == NBLK - 1) {
                gBarCnt = 0;
                __threadfence();
                atomicExch(&gBarPhase, target);
            } else {
                while ((int)(atomicAdd(&gBarPhase, 0u) - target) < 0) {
                    __nanosleep(64);
                }
            }
        }
        __syncthreads();
    }
}

// ------------------------- classifier ------------------------------------
__global__ void classifier_kernel(const float* __restrict__ w1, const float* __restrict__ b1,
                                  const float* __restrict__ w2, const float* __restrict__ b2,
                                  float* __restrict__ d_out) {
    __shared__ float hid[300];
    int b = blockIdx.x;
    int tid = threadIdx.x, warp = tid >> 5, lane = tid & 31;
    const float* hb = d_out + OUT_HENC + (long)b * NHH;

    for (int j = warp; j < 300; j += 8) {
        float s = 0.f;
        for (int k = lane; k < NHH; k += 32) s += hb[k] * w1[(long)j * NHH + k];
#pragma unroll
        for (int off = 16; off; off >>= 1) s += __shfl_xor_sync(0xffffffffu, s, off);
        if (lane == 0) hid[j] = fmaxf(s + b1[j], 0.f);
    }
    __syncthreads();
    if (warp < 2) {
        float s = 0.f;
        for (int j = lane; j < 300; j += 32) s += hid[j] * w2[warp * 300 + j];
#pragma unroll
        for (int off = 16; off; off >>= 1) s += __shfl_xor_sync(0xffffffffu, s, off);
        if (lane == 0) d_out[OUT_CLS + b * 2 + warp] = s + b2[warp];
    }
}

// ------------------------- launch ----------------------------------------
extern "C" void kernel_launch(void* const* d_in, const int* in_sizes, int n_in,
                              void* d_out, int out_size) {
    const float* x      = (const float*)d_in[0];
    const float* adj    = (const float*)d_in[1];
    const float* h0     = (const float*)d_in[3];
    const float* conv_w = (const float*)d_in[4];
    const float* conv_b = (const float*)d_in[5];
    const float* w_ih   = (const float*)d_in[6];
    const float* w_hh   = (const float*)d_in[7];
    const float* b_ih   = (const float*)d_in[8];
    const float* b_hh   = (const float*)d_in[9];
    const float* cls_w1 = (const float*)d_in[10];
    const float* cls_b1 = (const float*)d_in[11];
    const float* cls_w2 = (const float*)d_in[12];
    const float* cls_b2 = (const float*)d_in[13];
    float* out = (float*)d_out;

    const int REPR_SMEM = (128 * 129 + 32 * 132 + 32 * 132 + 12 * 128) * 4;  // 105984
    const int GX_SMEM   = 3 * (128 + 128) * 72 * 2;                          // 110592
    const int PS_SMEM   = 4 * (32 + 96) * 72 * 2 + 32 * 100 * 4;             // 86528
    cudaFuncSetAttribute(repr_kernel, cudaFuncAttributeMaxDynamicSharedMemorySize, REPR_SMEM);
    cudaFuncSetAttribute(gemm_gx_kernel, cudaFuncAttributeMaxDynamicSharedMemorySize, GX_SMEM);
    cudaFuncSetAttribute(gru_persistent_kernel, cudaFuncAttributeMaxDynamicSharedMemorySize, PS_SMEM);

    convert_weights_kernel<<<2048, 256>>>((const float4*)w_ih, (const float4*)w_hh);
    support_kernel<<<1, 128>>>(adj);
    repr_kernel<<<NR, 256, REPR_SMEM>>>(x, conv_w, conv_b, out);
    h_init_kernel<<<512, 256>>>(h0);

    gemm_gx_kernel<<<dim3(96, 25), 256, GX_SMEM>>>(b_ih);

    gru_persistent_kernel<<<NBLK, 256, PS_SMEM>>>(h0, b_hh, out);

    classifier_kernel<<<NB, 256>>>(cls_w1, cls_b1, cls_w2, cls_b2, out);
}